// round 1
// baseline (speedup 1.0000x reference)
#include <cuda_runtime.h>

// Problem constants (from reference): VOCAB=32000, D=512, B=8, S=4096.
#define BATCH 8
#define SEQ   4096
#define DMODEL 512

// One CTA per sequence position s. 128 threads, each owns 4 contiguous d's
// (float4). PE for (s, d0..d0+3) is computed ONCE per CTA and reused across
// all 8 batch rows — this cuts transcendental work 8x vs per-output-element,
// keeping the kernel DRAM-bound instead of MUFU-bound.
//
// PE (faithful to reference): angle = s / 10000^(2*i/D) for EVERY i;
// even i -> sin(angle), odd i -> cos(angle).
__global__ void __launch_bounds__(128, 8)
embed_pe_kernel(const int* __restrict__ tokens,
                const float* __restrict__ table,
                float* __restrict__ out)
{
    const int s  = blockIdx.x;          // 0..SEQ-1
    const int t  = threadIdx.x;         // 0..127
    const int d0 = t << 2;              // 0,4,...,508

    // --- PE for this (s, d0..d0+3) ---
    const float ps = (float)s;
    float pe[4];
#pragma unroll
    for (int j = 0; j < 4; ++j) {
        const int   di = d0 + j;
        const float fi = (float)di;
        // 10000^(2*i/D) = exp2( (2*i/D) * log2(10000) )
        const float w  = exp2f(fi * (2.0f / (float)DMODEL) * 13.287712379549449f);
        const float angle = ps / w;
        pe[j] = (di & 1) ? cosf(angle) : sinf(angle);
    }

    // --- broadcast the 8 tokens for this position ---
    __shared__ int toks[BATCH];
    if (t < BATCH) toks[t] = tokens[t * SEQ + s];
    __syncthreads();

    // --- gather + add + store, 8 batch rows ---
#pragma unroll
    for (int b = 0; b < BATCH; ++b) {
        const float4 e = *reinterpret_cast<const float4*>(
            table + (size_t)toks[b] * DMODEL + d0);
        float4 o;
        o.x = e.x + pe[0];
        o.y = e.y + pe[1];
        o.z = e.z + pe[2];
        o.w = e.w + pe[3];
        *reinterpret_cast<float4*>(
            out + ((size_t)(b * SEQ + s)) * DMODEL + d0) = o;
    }
}

extern "C" void kernel_launch(void* const* d_in, const int* in_sizes, int n_in,
                              void* d_out, int out_size)
{
    const int*   tokens = (const int*)d_in[0];   // [B, S] int32
    const float* table  = (const float*)d_in[1]; // [VOCAB, D] f32
    float*       out    = (float*)d_out;         // [B, S, D] f32
    (void)in_sizes; (void)n_in; (void)out_size;

    embed_pe_kernel<<<SEQ, 128>>>(tokens, table, out);
}

// round 2
// speedup vs baseline: 1.2163x; 1.2163x over previous
#include <cuda_runtime.h>

#define BATCH 8
#define SEQ   4096
#define DMODEL 512

// One CTA per sequence position s; 128 threads x float4 covers D=512.
// Pipeline inside each thread:
//   1) load the 8 token ids (uniform across the CTA -> broadcast LDG, no smem/barrier)
//   2) issue all 8 table float4 gathers (MLP=8, overlaps with step 3)
//   3) compute the 4 PE values (sin/cos) while gathers are in flight
//   4) add + streaming store (__stcs: output is write-once, keep the 65MB
//      embedding table resident in L2 instead)
__global__ void __launch_bounds__(128)
embed_pe_kernel(const int* __restrict__ tokens,
                const float* __restrict__ table,
                float* __restrict__ out)
{
    const int s  = blockIdx.x;          // 0..SEQ-1
    const int t  = threadIdx.x;         // 0..127
    const int d0 = t << 2;              // 0,4,...,508

    // 1) token ids for this position (uniform per CTA -> broadcast loads)
    int tok[BATCH];
#pragma unroll
    for (int b = 0; b < BATCH; ++b)
        tok[b] = __ldg(tokens + b * SEQ + s);

    // 2) fire all gathers
    float4 e[BATCH];
#pragma unroll
    for (int b = 0; b < BATCH; ++b)
        e[b] = *reinterpret_cast<const float4*>(
            table + (size_t)tok[b] * DMODEL + d0);

    // 3) PE for (s, d0..d0+3) — overlaps with the loads above
    const float ps = (float)s;
    float pe[4];
#pragma unroll
    for (int j = 0; j < 4; ++j) {
        const int   di = d0 + j;
        const float fi = (float)di;
        // 10000^(2*i/D) = exp2((2*i/D) * log2(10000))
        const float w  = exp2f(fi * (2.0f / (float)DMODEL) * 13.287712379549449f);
        const float angle = ps / w;
        pe[j] = (di & 1) ? cosf(angle) : sinf(angle);
    }

    // 4) add + streaming stores (evict-first: don't thrash L2)
#pragma unroll
    for (int b = 0; b < BATCH; ++b) {
        float4 o;
        o.x = e[b].x + pe[0];
        o.y = e[b].y + pe[1];
        o.z = e[b].z + pe[2];
        o.w = e[b].w + pe[3];
        __stcs(reinterpret_cast<float4*>(
                   out + ((size_t)(b * SEQ + s)) * DMODEL + d0), o);
    }
}

extern "C" void kernel_launch(void* const* d_in, const int* in_sizes, int n_in,
                              void* d_out, int out_size)
{
    const int*   tokens = (const int*)d_in[0];   // [B, S] int32
    const float* table  = (const float*)d_in[1]; // [VOCAB, D] f32
    float*       out    = (float*)d_out;         // [B, S, D] f32
    (void)in_sizes; (void)n_in; (void)out_size;

    embed_pe_kernel<<<SEQ, 128>>>(tokens, table, out);
}